// round 16
// baseline (speedup 1.0000x reference)
#include <cuda_runtime.h>

#define NN 4096
#define NJC 37                // j-chunks (grid.y); 16*37 = 592 blocks = 4/SM one wave
#define JCH 112               // j's per chunk (37*112 = 4144 >= 4096, rest sentinels)
#define NDUO (JCH / 2)        // 56 packed duos per chunk
#define IBLK 256
#define EPSF 1e-8f

// Per-chunk partial repulsive forces: g_rf[chunk][i]
__device__ float2 g_rf[NJC][NN];

typedef unsigned long long u64;

// ---- packed f32x2 helpers (sm_103a) --------------------------------------
__device__ __forceinline__ u64 pk2(float lo, float hi) {
    u64 r; asm("mov.b64 %0, {%1, %2};" : "=l"(r) : "f"(lo), "f"(hi)); return r;
}
__device__ __forceinline__ void upk2(u64 v, float& lo, float& hi) {
    asm("mov.b64 {%0, %1}, %2;" : "=f"(lo), "=f"(hi) : "l"(v));
}
__device__ __forceinline__ u64 add2(u64 a, u64 b) {
    u64 r; asm("add.rn.f32x2 %0, %1, %2;" : "=l"(r) : "l"(a), "l"(b)); return r;
}
__device__ __forceinline__ u64 mul2(u64 a, u64 b) {
    u64 r; asm("mul.rn.f32x2 %0, %1, %2;" : "=l"(r) : "l"(a), "l"(b)); return r;
}
__device__ __forceinline__ u64 fma2(u64 a, u64 b, u64 c) {
    u64 r; asm("fma.rn.f32x2 %0, %1, %2, %3;" : "=l"(r) : "l"(a), "l"(b), "l"(c)); return r;
}
__device__ __forceinline__ float ex2a(float x) {
    float r; asm("ex2.approx.ftz.f32 %0, %1;" : "=f"(r) : "f"(x)); return r;
}
__device__ __forceinline__ float rsqa(float x) {
    float r; asm("rsqrt.approx.ftz.f32 %0, %1;" : "=f"(r) : "f"(x)); return r;
}

// Pair-loop context: packed constants + accumulators (no macros — R11 lesson)
struct PairCtx {
    u64 xi2, yi2, eps2, nC1, C0, nh, c1p5;
    u64 fx2, fy2;
};

// duo A: MUFU rsqrt path (4 MUFU, 9 f32x2-fma per duo)
__device__ __forceinline__ void duoA(PairCtx& c, u64 sx, u64 sy) {
    u64 dx = add2(c.xi2, sx);
    u64 dy = add2(c.yi2, sy);
    u64 t  = fma2(dx, dx, c.eps2);
    t      = fma2(dy, dy, t);
    float t0, t1; upk2(t, t0, t1);
    u64 inv = pk2(rsqa(t0), rsqa(t1));
    u64 d   = mul2(t, inv);
    u64 arg = fma2(d, c.nC1, c.C0);
    float a0, a1; upk2(arg, a0, a1);
    u64 e = pk2(ex2a(a0), ex2a(a1));
    u64 s = mul2(e, inv);
    c.fx2 = fma2(s, dx, c.fx2);
    c.fy2 = fma2(s, dy, c.fy2);
}

// duo B: soft rsqrt, magic + 1 packed Newton (2 MUFU, 12 f32x2-fma + alu)
__device__ __forceinline__ void duoB(PairCtx& c, u64 sx, u64 sy) {
    u64 dx = add2(c.xi2, sx);
    u64 dy = add2(c.yi2, sy);
    u64 t  = fma2(dx, dx, c.eps2);
    t      = fma2(dy, dy, t);
    float t0, t1; upk2(t, t0, t1);
    float g0 = __uint_as_float(0x5F3759DFu - (__float_as_uint(t0) >> 1));
    float g1 = __uint_as_float(0x5F3759DFu - (__float_as_uint(t1) >> 1));
    u64 y = pk2(g0, g1);
    u64 p = mul2(mul2(t, c.nh), y);          // -0.5*t*y
    u64 q = fma2(p, y, c.c1p5);              // 1.5 - 0.5*t*y*y
    u64 inv = mul2(y, q);                    // refined 1/sqrt(t)
    u64 d   = mul2(t, inv);
    u64 arg = fma2(d, c.nC1, c.C0);
    float a0, a1; upk2(arg, a0, a1);
    u64 e = pk2(ex2a(a0), ex2a(a1));
    u64 s = mul2(e, inv);
    c.fx2 = fma2(s, dx, c.fx2);
    c.fy2 = fma2(s, dy, c.fy2);
}

// ---------------------------------------------------------------------------
// Kernel 1: pairwise forces, f32x2-packed, MUFU/FMA pipe-balanced at A:B=1:2
// (per 6 pairs: MUFU 8 ops=64cyc vs fma 33 ops=66cyc -> ~11 cyc/pair floor).
// mag/d = 10*exp((0.6-d)/0.71)/d = exp2(fma(d,-C1,C0))/d
//   C1 = log2(e)/0.71 = 2.0319649, C0 = 0.6*C1 + log2(10) = 4.5411070
// Diagonal j==i contributes exactly 0 (dx=dy=0); sentinel j>=NN -> exp2(-huge)=0.
// ---------------------------------------------------------------------------
__global__ __launch_bounds__(IBLK, 4) void pair_kernel(const float4* __restrict__ state) {
    __shared__ u64 snx[NDUO], sny[NDUO];   // NEGATED packed j positions

    const int i     = blockIdx.x * IBLK + threadIdx.x;
    const int jbase = blockIdx.y * JCH;

    if (threadIdx.x < NDUO) {
        int j0 = jbase + 2 * threadIdx.x;
        float x0 = 1e9f, y0 = 1e9f, x1 = 1e9f, y1 = 1e9f;
        if (j0 < NN)     { float4 s = state[j0];     x0 = -s.x; y0 = -s.y; }
        if (j0 + 1 < NN) { float4 s = state[j0 + 1]; x1 = -s.x; y1 = -s.y; }
        snx[threadIdx.x] = pk2(x0, x1);
        sny[threadIdx.x] = pk2(y0, y1);
    }
    __syncthreads();

    const float4 si = state[i];
    PairCtx c;
    c.xi2  = pk2(si.x, si.x);
    c.yi2  = pk2(si.y, si.y);
    c.eps2 = pk2(EPSF, EPSF);
    c.nC1  = pk2(-2.0319649f, -2.0319649f);
    c.C0   = pk2(4.5411070f, 4.5411070f);
    c.nh   = pk2(-0.5f, -0.5f);
    c.c1p5 = pk2(1.5f, 1.5f);
    c.fx2  = pk2(0.0f, 0.0f);
    c.fy2  = c.fx2;

    // 18 groups of (A,B,B) = 54 duos, then (A,B) = 2 duos -> 19 A : 37 B
#pragma unroll 2
    for (int g = 0; g < 18; g++) {
        int jj = g * 3;
        duoA(c, snx[jj],     sny[jj]);
        duoB(c, snx[jj + 1], sny[jj + 1]);
        duoB(c, snx[jj + 2], sny[jj + 2]);
    }
    duoA(c, snx[54], sny[54]);
    duoB(c, snx[55], sny[55]);

    float lo, hi;
    upk2(c.fx2, lo, hi); float pfx = lo + hi;
    upk2(c.fy2, lo, hi); float pfy = lo + hi;
    g_rf[blockIdx.y][i] = make_float2(pfx, pfy);
}

// ---------------------------------------------------------------------------
// Kernel 2 (EXACT R5 structure — best measured): fused warp-split epilogue.
// 128 blocks x 256 threads. Block owns 32 agents. Warp w sums chunks
// c = w, w+8, ... for its 32 agents AND agent-0's partial in the same loop;
// shared combine; warp 0 integrates + writes out + cost.
// Chunk order identical for out[0] and recomputed o0 -> bitwise equal.
// ---------------------------------------------------------------------------
__device__ __forceinline__ float4 integrate(float4 s, float2 g, float2 rf, float des) {
    float tx = g.x - s.x, ty = g.y - s.y;
    float dist = sqrtf(fmaf(tx, tx, fmaf(ty, ty, EPSF)));
    float k = des / dist;
    float Fx = rf.x + 2.0f * (tx * k - s.z);         // K = 2
    float Fy = rf.y + 2.0f * (ty * k - s.w);
    float vx = fmaf(Fx, 0.1f / 60.0f, s.z);          // vel + F/mass*dt
    float vy = fmaf(Fy, 0.1f / 60.0f, s.w);
    float sp = sqrtf(fmaf(vx, vx, fmaf(vy, vy, EPSF)));
    float sc = fminf(1.0f, 1.4f / sp);
    vx *= sc; vy *= sc;
    return make_float4(fmaf(vx, 0.1f, s.x), fmaf(vy, 0.1f, s.y), vx, vy);
}

__global__ __launch_bounds__(256) void epilogue_kernel(const float4* __restrict__ state,
                                                       const float2* __restrict__ goals,
                                                       const float* __restrict__ cost_in,
                                                       const float* __restrict__ rip,
                                                       const float* __restrict__ goal,
                                                       float4* __restrict__ out,
                                                       float* __restrict__ cost_out) {
    __shared__ float2 s_acc[8][32];
    __shared__ float2 s_r0[8];

    const int lane = threadIdx.x & 31;
    const int w    = threadIdx.x >> 5;
    const int i    = blockIdx.x * 32 + lane;

    float fx = 0.0f, fy = 0.0f, r0x = 0.0f, r0y = 0.0f;
    for (int c = w; c < NJC; c += 8) {
        float2 p = g_rf[c][i];
        fx += p.x; fy += p.y;
        float2 q = g_rf[c][0];            // broadcast load
        r0x += q.x; r0y += q.y;
    }
    s_acc[w][lane] = make_float2(fx, fy);
    if (lane == 0) s_r0[w] = make_float2(r0x, r0y);
    __syncthreads();

    if (w == 0) {
        float2 rf  = make_float2(0.0f, 0.0f);
        float2 rf0 = make_float2(0.0f, 0.0f);
#pragma unroll
        for (int k = 0; k < 8; k++) {
            float2 p = s_acc[k][lane];
            rf.x += p.x; rf.y += p.y;
            float2 q = s_r0[k];
            rf0.x += q.x; rf0.y += q.y;
        }

        float4 oi = integrate(state[i], goals[i], rf, (i == 0) ? 1.0f : 1.4f);
        out[i] = oi;

        // Agent-0 pose: same partial order as the i==0 path -> bitwise equal.
        float4 o0 = (i == 0) ? oi : integrate(state[0], goals[0], rf0, 1.0f);

        float g0 = goal[0], g1 = goal[1];
        float a0 = rip[0] - g0, a1 = rip[1] - g1;
        float b0 = o0.x - g0,  b1 = o0.y - g1;
        float pg = sqrtf(fmaf(a0, a0, fmaf(a1, a1, EPSF)))
                 - sqrtf(fmaf(b0, b0, fmaf(b1, b1, EPSF)));

        float dx = oi.x - o0.x, dy = oi.y - o0.y;
        float dr = sqrtf(fmaf(dx, dx, fmaf(dy, dy, EPSF)));
        float e  = ex2a(dr * (-1.4426950408889634f / 1.5f));  // exp(-dr/1.5)

        cost_out[i] = cost_in[i] + fmaf(2.0f, e, 5.0f * pg);
    }
}

// ---------------------------------------------------------------------------
// Inputs (metadata order): state[N,4], cost[N,1], goals[N,2],
// robot_init_pose[2], goal[2]. Output: out[N,4] then new_cost[N,1].
// ---------------------------------------------------------------------------
extern "C" void kernel_launch(void* const* d_in, const int* in_sizes, int n_in,
                              void* d_out, int out_size) {
    const float* state = (const float*)d_in[0];
    const float* cost  = (const float*)d_in[1];
    const float* goals = (const float*)d_in[2];
    const float* rip   = (const float*)d_in[3];
    const float* goal  = (const float*)d_in[4];
    float* out = (float*)d_out;

    dim3 grid1(NN / IBLK, NJC);          // 16 x 37 = 592 blocks = 4/SM, one wave
    pair_kernel<<<grid1, IBLK>>>((const float4*)state);
    epilogue_kernel<<<NN / 32, 256>>>((const float4*)state, (const float2*)goals,
                                      cost, rip, goal,
                                      (float4*)out, out + NN * 4);
}

// round 17
// speedup vs baseline: 1.1555x; 1.1555x over previous
#include <cuda_runtime.h>

#define NN 4096
#define NJC 37                // j-chunks (grid.y); 16*37 = 592 blocks = 4/SM one wave
#define JCH 112               // j's per chunk (37*112 = 4144 >= 4096, rest sentinels)
#define NDUO (JCH / 2)        // 56 packed duos per chunk
#define IBLK 256
#define EPSF 1e-8f

// Per-chunk partial repulsive forces: g_rf[chunk][i]
__device__ float2 g_rf[NJC][NN];

typedef unsigned long long u64;

// ---- packed f32x2 helpers (sm_103a) --------------------------------------
__device__ __forceinline__ u64 pk2(float lo, float hi) {
    u64 r; asm("mov.b64 %0, {%1, %2};" : "=l"(r) : "f"(lo), "f"(hi)); return r;
}
__device__ __forceinline__ void upk2(u64 v, float& lo, float& hi) {
    asm("mov.b64 {%0, %1}, %2;" : "=f"(lo), "=f"(hi) : "l"(v));
}
__device__ __forceinline__ u64 add2(u64 a, u64 b) {
    u64 r; asm("add.rn.f32x2 %0, %1, %2;" : "=l"(r) : "l"(a), "l"(b)); return r;
}
__device__ __forceinline__ u64 mul2(u64 a, u64 b) {
    u64 r; asm("mul.rn.f32x2 %0, %1, %2;" : "=l"(r) : "l"(a), "l"(b)); return r;
}
__device__ __forceinline__ u64 fma2(u64 a, u64 b, u64 c) {
    u64 r; asm("fma.rn.f32x2 %0, %1, %2, %3;" : "=l"(r) : "l"(a), "l"(b), "l"(c)); return r;
}
__device__ __forceinline__ float ex2a(float x) {
    float r; asm("ex2.approx.ftz.f32 %0, %1;" : "=f"(r) : "f"(x)); return r;
}
__device__ __forceinline__ float rsqa(float x) {
    float r; asm("rsqrt.approx.ftz.f32 %0, %1;" : "=f"(r) : "f"(x)); return r;
}

// ---------------------------------------------------------------------------
// Kernel 1: EXACT R5 pair kernel (best measured) + PDL launch_dependents.
// f32x2-packed, MUFU/FMA balanced at A:B = 1:1.
// mag/d = 10*exp((0.6-d)/0.71)/d = exp2(fma(d,-C1,C0))/d
//   C1 = log2(e)/0.71 = 2.0319649, C0 = 0.6*C1 + log2(10) = 4.5411070
// Diagonal j==i contributes exactly 0; sentinel j>=NN -> exp2(-huge)=0.
// ---------------------------------------------------------------------------
__global__ __launch_bounds__(IBLK, 4) void pair_kernel(const float4* __restrict__ state) {
    __shared__ u64 snx[NDUO], sny[NDUO];   // NEGATED packed j positions

    const int i     = blockIdx.x * IBLK + threadIdx.x;
    const int jbase = blockIdx.y * JCH;

    if (threadIdx.x < NDUO) {
        int j0 = jbase + 2 * threadIdx.x;
        float x0 = 1e9f, y0 = 1e9f, x1 = 1e9f, y1 = 1e9f;
        if (j0 < NN)     { float4 s = state[j0];     x0 = -s.x; y0 = -s.y; }
        if (j0 + 1 < NN) { float4 s = state[j0 + 1]; x1 = -s.x; y1 = -s.y; }
        snx[threadIdx.x] = pk2(x0, x1);
        sny[threadIdx.x] = pk2(y0, y1);
    }
    __syncthreads();

    // PDL: allow the epilogue grid to launch & ramp while we compute.
    asm volatile("griddepcontrol.launch_dependents;");

    const float4 si = state[i];
    const u64 xi2   = pk2(si.x, si.x);
    const u64 yi2   = pk2(si.y, si.y);
    const u64 eps2  = pk2(EPSF, EPSF);
    const u64 nC1_2 = pk2(-2.0319649f, -2.0319649f);
    const u64 C0_2  = pk2(4.5411070f, 4.5411070f);
    const u64 nh2   = pk2(-0.5f, -0.5f);
    const u64 c1p5  = pk2(1.5f, 1.5f);

    u64 fx2 = pk2(0.0f, 0.0f);
    u64 fy2 = fx2;

#pragma unroll 4
    for (int jj = 0; jj < NDUO; jj += 2) {
        {   // duo A: MUFU rsqrt path
            u64 dx = add2(xi2, snx[jj]);
            u64 dy = add2(yi2, sny[jj]);
            u64 t  = fma2(dx, dx, eps2);
            t      = fma2(dy, dy, t);
            float t0, t1; upk2(t, t0, t1);
            u64 inv = pk2(rsqa(t0), rsqa(t1));
            u64 d   = mul2(t, inv);
            u64 arg = fma2(d, nC1_2, C0_2);
            float a0, a1; upk2(arg, a0, a1);
            u64 e = pk2(ex2a(a0), ex2a(a1));
            u64 s = mul2(e, inv);
            fx2 = fma2(s, dx, fx2);
            fy2 = fma2(s, dy, fy2);
        }
        {   // duo B: soft rsqrt (magic + 1 packed Newton) -> frees MUFU pipe
            u64 dx = add2(xi2, snx[jj + 1]);
            u64 dy = add2(yi2, sny[jj + 1]);
            u64 t  = fma2(dx, dx, eps2);
            t      = fma2(dy, dy, t);
            float t0, t1; upk2(t, t0, t1);
            float g0 = __uint_as_float(0x5F3759DFu - (__float_as_uint(t0) >> 1));
            float g1 = __uint_as_float(0x5F3759DFu - (__float_as_uint(t1) >> 1));
            u64 y = pk2(g0, g1);
            u64 p = mul2(mul2(t, nh2), y);
            u64 q = fma2(p, y, c1p5);
            u64 inv = mul2(y, q);
            u64 d   = mul2(t, inv);
            u64 arg = fma2(d, nC1_2, C0_2);
            float a0, a1; upk2(arg, a0, a1);
            u64 e = pk2(ex2a(a0), ex2a(a1));
            u64 s = mul2(e, inv);
            fx2 = fma2(s, dx, fx2);
            fy2 = fma2(s, dy, fy2);
        }
    }

    float lo, hi;
    upk2(fx2, lo, hi); float pfx = lo + hi;
    upk2(fy2, lo, hi); float pfy = lo + hi;
    g_rf[blockIdx.y][i] = make_float2(pfx, pfy);
}

// ---------------------------------------------------------------------------
// Kernel 2: EXACT R5 warp-split epilogue, launched with PDL.
// griddepcontrol.wait parks until the pair grid fully completes (memory
// visible), but the launch/ramp already happened under the pair kernel.
// ---------------------------------------------------------------------------
__device__ __forceinline__ float4 integrate(float4 s, float2 g, float2 rf, float des) {
    float tx = g.x - s.x, ty = g.y - s.y;
    float dist = sqrtf(fmaf(tx, tx, fmaf(ty, ty, EPSF)));
    float k = des / dist;
    float Fx = rf.x + 2.0f * (tx * k - s.z);         // K = 2
    float Fy = rf.y + 2.0f * (ty * k - s.w);
    float vx = fmaf(Fx, 0.1f / 60.0f, s.z);          // vel + F/mass*dt
    float vy = fmaf(Fy, 0.1f / 60.0f, s.w);
    float sp = sqrtf(fmaf(vx, vx, fmaf(vy, vy, EPSF)));
    float sc = fminf(1.0f, 1.4f / sp);
    vx *= sc; vy *= sc;
    return make_float4(fmaf(vx, 0.1f, s.x), fmaf(vy, 0.1f, s.y), vx, vy);
}

__global__ __launch_bounds__(256) void epilogue_kernel(const float4* __restrict__ state,
                                                       const float2* __restrict__ goals,
                                                       const float* __restrict__ cost_in,
                                                       const float* __restrict__ rip,
                                                       const float* __restrict__ goal,
                                                       float4* __restrict__ out,
                                                       float* __restrict__ cost_out) {
    __shared__ float2 s_acc[8][32];
    __shared__ float2 s_r0[8];

    const int lane = threadIdx.x & 31;
    const int w    = threadIdx.x >> 5;
    const int i    = blockIdx.x * 32 + lane;

    // Wait for the pair grid (PDL). Everything above overlapped its execution.
    asm volatile("griddepcontrol.wait;" ::: "memory");

    float fx = 0.0f, fy = 0.0f, r0x = 0.0f, r0y = 0.0f;
    for (int c = w; c < NJC; c += 8) {
        float2 p = g_rf[c][i];
        fx += p.x; fy += p.y;
        float2 q = g_rf[c][0];            // broadcast load
        r0x += q.x; r0y += q.y;
    }
    s_acc[w][lane] = make_float2(fx, fy);
    if (lane == 0) s_r0[w] = make_float2(r0x, r0y);
    __syncthreads();

    if (w == 0) {
        float2 rf  = make_float2(0.0f, 0.0f);
        float2 rf0 = make_float2(0.0f, 0.0f);
#pragma unroll
        for (int k = 0; k < 8; k++) {
            float2 p = s_acc[k][lane];
            rf.x += p.x; rf.y += p.y;
            float2 q = s_r0[k];
            rf0.x += q.x; rf0.y += q.y;
        }

        float4 oi = integrate(state[i], goals[i], rf, (i == 0) ? 1.0f : 1.4f);
        out[i] = oi;

        // Agent-0 pose: same partial order as the i==0 path -> bitwise equal.
        float4 o0 = (i == 0) ? oi : integrate(state[0], goals[0], rf0, 1.0f);

        float g0 = goal[0], g1 = goal[1];
        float a0 = rip[0] - g0, a1 = rip[1] - g1;
        float b0 = o0.x - g0,  b1 = o0.y - g1;
        float pg = sqrtf(fmaf(a0, a0, fmaf(a1, a1, EPSF)))
                 - sqrtf(fmaf(b0, b0, fmaf(b1, b1, EPSF)));

        float dx = oi.x - o0.x, dy = oi.y - o0.y;
        float dr = sqrtf(fmaf(dx, dx, fmaf(dy, dy, EPSF)));
        float e  = ex2a(dr * (-1.4426950408889634f / 1.5f));  // exp(-dr/1.5)

        cost_out[i] = cost_in[i] + fmaf(2.0f, e, 5.0f * pg);
    }
}

// ---------------------------------------------------------------------------
// Inputs (metadata order): state[N,4], cost[N,1], goals[N,2],
// robot_init_pose[2], goal[2]. Output: out[N,4] then new_cost[N,1].
// ---------------------------------------------------------------------------
extern "C" void kernel_launch(void* const* d_in, const int* in_sizes, int n_in,
                              void* d_out, int out_size) {
    const float* state = (const float*)d_in[0];
    const float* cost  = (const float*)d_in[1];
    const float* goals = (const float*)d_in[2];
    const float* rip   = (const float*)d_in[3];
    const float* goal  = (const float*)d_in[4];
    float* out = (float*)d_out;

    dim3 grid1(NN / IBLK, NJC);          // 16 x 37 = 592 blocks = 4/SM, one wave
    pair_kernel<<<grid1, IBLK>>>((const float4*)state);

    // Epilogue with Programmatic Dependent Launch: launches during pair_kernel,
    // blocks in griddepcontrol.wait until the pair grid completes.
    cudaLaunchConfig_t cfg = {};
    cfg.gridDim  = dim3(NN / 32);        // 128 blocks
    cfg.blockDim = dim3(256);
    cfg.dynamicSmemBytes = 0;
    cfg.stream = 0;                      // same (capture) stream as pair_kernel
    cudaLaunchAttribute attrs[1];
    attrs[0].id = cudaLaunchAttributeProgrammaticStreamSerialization;
    attrs[0].val.programmaticStreamSerializationAllowed = 1;
    cfg.attrs = attrs;
    cfg.numAttrs = 1;
    cudaLaunchKernelEx(&cfg, epilogue_kernel,
                       (const float4*)state, (const float2*)goals,
                       cost, rip, goal,
                       (float4*)out, out + NN * 4);
}